// round 1
// baseline (speedup 1.0000x reference)
#include <cuda_runtime.h>
#include <math.h>

#define NB 32
#define NK 17
#define HWPIX 4096
#define HID 256
#define ICC 8

typedef unsigned long long u64;

__device__ __forceinline__ u64 pack2(float lo, float hi){
  u64 r; asm("mov.b64 %0, {%1,%2};" : "=l"(r) : "f"(lo), "f"(hi)); return r;
}
__device__ __forceinline__ void unpack2(u64 v, float& lo, float& hi){
  asm("mov.b64 {%0,%1}, %2;" : "=f"(lo), "=f"(hi) : "l"(v));
}
__device__ __forceinline__ u64 fma2(u64 a, u64 b, u64 c){
  u64 d; asm("fma.rn.f32x2 %0, %1, %2, %3;" : "=l"(d) : "l"(a), "l"(b), "l"(c)); return d;
}

// ---- static scratch (allocation-free rule) ----
__device__ float g_buf1[NB * HID * HWPIX];      // 134 MB
__device__ float g_buf2[NB * HID * HWPIX];      // 134 MB
// transformed weights: [ic][tap][2*OC] with each weight duplicated (f32x2 lanes) and BN scale folded
// offsets: s1:0  s2:1179648  h1:2359296  o1:3538944  v1:4718592 (v1 OC=128 -> 589824)
__device__ float g_wt[5308416];
__device__ float g_cg[NB * NK * 2];

// ---- weight transform: w[oc][ic][3][3] * (g[oc]/sqrt(1+eps)) -> wT2[ic][tap][2*oc (dup)] ----
__global__ void wtrans2_kernel(const float* __restrict__ w, const float* __restrict__ g,
                               float* __restrict__ wT2, int IC, int OC)
{
  int idx = blockIdx.x * 256 + threadIdx.x;
  int n = OC * IC * 9;
  if (idx >= n) return;
  int t  = idx % 9;
  int ic = (idx / 9) % IC;
  int oc = idx / (9 * IC);
  float scale = g[oc] * rsqrtf(1.0f + 1e-5f);
  float v = w[idx] * scale;
  size_t o = ((size_t)(ic * 9 + t)) * (2 * OC) + 2 * oc;
  wT2[o] = v;
  wT2[o + 1] = v;
}

// ---- 3x3 conv + (folded BN) + bias + ReLU, SAME padding. IC always 256 here. ----
// block: 64 oc x (16x16 px), 256 threads, per-thread 8oc x 8px as f32x2 pairs.
__global__ __launch_bounds__(256, 2)
void conv3x3_kernel(const float* __restrict__ x, const float* __restrict__ wT2,
                    const float* __restrict__ bias, float* __restrict__ y,
                    int IC, int OC)
{
  __shared__ float ws2[ICC][9][128];   // 36 KB  (ic, tap, dup-oc pairs)
  __shared__ float xs[ICC][18][20];    // 11.5 KB (halo tile, pad to 20 for alignment)

  const int b    = blockIdx.z;
  const int oc0  = blockIdx.y << 6;
  const int tile = blockIdx.x;
  const int ty0  = (tile >> 2) << 4;
  const int tx0  = (tile & 3) << 4;
  const int tid  = threadIdx.x;
  const int warp = tid >> 5;           // oc group (warp-uniform -> broadcast w loads)
  const int lane = tid & 31;
  const int prow = lane >> 1;          // 0..15
  const int pcol = (lane & 1) << 3;    // 0 or 8

  const float* xb = x + (size_t)b * IC * HWPIX;

  u64 acc2[8][4];
  #pragma unroll
  for (int o = 0; o < 8; o++)
    #pragma unroll
    for (int jj = 0; jj < 4; jj++) acc2[o][jj] = 0ULL;

  float* wsflat = &ws2[0][0][0];

  for (int ic0 = 0; ic0 < IC; ic0 += ICC) {
    // fill weight chunk: 8*9*128 = 9216 floats, fully coalesced
    const float* wsrc = wT2 + ((size_t)ic0 * 9) * (2 * OC) + 2 * oc0;
    #pragma unroll
    for (int k = 0; k < 36; k++) {
      int q  = tid + (k << 8);
      int o2 = q & 127;
      int r  = q >> 7;                // i*9 + t
      wsflat[q] = wsrc[(size_t)r * (2 * OC) + o2];
    }
    // fill input chunk with halo, zero-padded
    for (int q = tid; q < ICC * 18 * 18; q += 256) {
      int rx = q % 18;
      int t2 = q / 18;
      int ry = t2 % 18;
      int i  = t2 / 18;
      int gy = ty0 + ry - 1;
      int gx = tx0 + rx - 1;
      float v = 0.f;
      if ((unsigned)gy < 64u && (unsigned)gx < 64u)
        v = xb[(size_t)(ic0 + i) * HWPIX + (gy << 6) + gx];
      xs[i][ry][rx] = v;
    }
    __syncthreads();

    #pragma unroll 1
    for (int i = 0; i < ICC; i++) {
      #pragma unroll
      for (int ky = 0; ky < 3; ky++) {
        const float* xr0 = &xs[i][prow + ky][pcol];
        float xrr[10];
        float4 a0 = *(const float4*)xr0;
        float4 a1 = *(const float4*)(xr0 + 4);
        xrr[0]=a0.x; xrr[1]=a0.y; xrr[2]=a0.z; xrr[3]=a0.w;
        xrr[4]=a1.x; xrr[5]=a1.y; xrr[6]=a1.z; xrr[7]=a1.w;
        xrr[8]=xr0[8]; xrr[9]=xr0[9];
        #pragma unroll
        for (int kx = 0; kx < 3; kx++) {
          const int t = ky * 3 + kx;
          const ulonglong2* wp2 = (const ulonglong2*)&ws2[i][t][warp << 4];
          ulonglong2 wa = wp2[0], wb = wp2[1], wc = wp2[2], wd = wp2[3];
          u64 wv[8] = {wa.x, wa.y, wb.x, wb.y, wc.x, wc.y, wd.x, wd.y};
          u64 xpt[4];
          #pragma unroll
          for (int jj = 0; jj < 4; jj++)
            xpt[jj] = pack2(xrr[kx + 2 * jj], xrr[kx + 2 * jj + 1]);
          #pragma unroll
          for (int o = 0; o < 8; o++)
            #pragma unroll
            for (int jj = 0; jj < 4; jj++)
              acc2[o][jj] = fma2(xpt[jj], wv[o], acc2[o][jj]);
        }
      }
    }
    __syncthreads();
  }

  #pragma unroll
  for (int o = 0; o < 8; o++) {
    int oc = oc0 + (warp << 3) + o;
    float bv = bias[oc];
    float vout[8];
    #pragma unroll
    for (int jj = 0; jj < 4; jj++) {
      float lo, hi; unpack2(acc2[o][jj], lo, hi);
      vout[2 * jj]     = fmaxf(lo + bv, 0.f);
      vout[2 * jj + 1] = fmaxf(hi + bv, 0.f);
    }
    float* yp = y + ((size_t)b * OC + oc) * HWPIX + ((ty0 + prow) << 6) + tx0 + pcol;
    *(float4*)yp       = make_float4(vout[0], vout[1], vout[2], vout[3]);
    *(float4*)(yp + 4) = make_float4(vout[4], vout[5], vout[6], vout[7]);
  }
}

__device__ __forceinline__ float softplusf(float x){
  return fmaxf(x, 0.f) + log1pf(expf(-fabsf(x)));
}

// ---- 1x1 conv head: y[b,o,p] = sum_ic w[o,ic]*x[b,ic,p] + bias[o]; optional softplus ----
template<int OC>
__global__ __launch_bounds__(256)
void conv1x1_kernel(const float* __restrict__ x, const float* __restrict__ w,
                    const float* __restrict__ bias, float* __restrict__ y,
                    int IC, int act)
{
  __shared__ float ws[OC * 256];
  int b = blockIdx.y;
  int tid = threadIdx.x;
  int n = OC * IC;
  for (int q = tid; q < n; q += 256) ws[q] = w[q];
  __syncthreads();
  int pix = blockIdx.x * 256 + tid;
  const float* xp = x + (size_t)b * IC * HWPIX + pix;
  float acc[OC];
  #pragma unroll
  for (int o = 0; o < OC; o++) acc[o] = bias[o];
  for (int ic = 0; ic < IC; ic += 4) {
    float x0 = xp[(size_t)ic * HWPIX];
    float x1 = xp[(size_t)(ic + 1) * HWPIX];
    float x2 = xp[(size_t)(ic + 2) * HWPIX];
    float x3 = xp[(size_t)(ic + 3) * HWPIX];
    #pragma unroll
    for (int o = 0; o < OC; o++) {
      float4 w4 = *(const float4*)&ws[o * IC + ic];
      acc[o] += w4.x * x0 + w4.y * x1 + w4.z * x2 + w4.w * x3;
    }
  }
  float* yp = y + ((size_t)b * OC) * HWPIX + pix;
  #pragma unroll
  for (int o = 0; o < OC; o++) {
    float v = acc[o];
    if (act) v = softplusf(v);
    yp[(size_t)o * HWPIX] = v;
  }
}

// ---- soft-argmax over 64x64 per (b,k): cg coords + scores(max) ----
__global__ void softargmax_kernel(const float* __restrict__ heat, float* __restrict__ cg,
                                  float* __restrict__ scores)
{
  int bk = blockIdx.x;
  const float* h = heat + (size_t)bk * HWPIX;
  int tid = threadIdx.x;
  __shared__ float r0[256], r1[256], r2[256];

  float m = -3.4e38f;
  for (int i = tid; i < HWPIX; i += 256) m = fmaxf(m, h[i]);
  r0[tid] = m; __syncthreads();
  for (int s = 128; s > 0; s >>= 1) { if (tid < s) r0[tid] = fmaxf(r0[tid], r0[tid + s]); __syncthreads(); }
  float M = r0[0];
  __syncthreads();

  float s = 0.f, sx = 0.f, sy = 0.f;
  for (int i = tid; i < HWPIX; i += 256) {
    float e = expf(h[i] - M);
    s += e; sx += e * (float)(i & 63); sy += e * (float)(i >> 6);
  }
  r0[tid] = s; r1[tid] = sx; r2[tid] = sy; __syncthreads();
  for (int st = 128; st > 0; st >>= 1) {
    if (tid < st) { r0[tid] += r0[tid + st]; r1[tid] += r1[tid + st]; r2[tid] += r2[tid + st]; }
    __syncthreads();
  }
  if (tid == 0) {
    cg[bk * 2]     = r1[0] / r0[0];
    cg[bk * 2 + 1] = r2[0] / r0[0];
    scores[bk] = M;
  }
}

// ---- local refine + combine + bilinear offset sampling + fw ----
__global__ void finalize_kernel(const float* __restrict__ heat, const float* __restrict__ off,
                                const float* __restrict__ cg, const float* __restrict__ alpha_p,
                                const float* __restrict__ fusion_p, float* __restrict__ coords_out,
                                float* __restrict__ fw_out)
{
  int idx = blockIdx.x * blockDim.x + threadIdx.x;
  float fw = 1.f / (1.f + expf(-fusion_p[0]));
  if (idx == 0) fw_out[0] = fw;
  if (idx >= NB * NK) return;
  float a = 1.f / (1.f + expf(-alpha_p[0]));
  float cgx = cg[idx * 2], cgy = cg[idx * 2 + 1];
  const float* hm = heat + (size_t)idx * HWPIX;

  int px = (int)rintf(fminf(fmaxf(cgx, 0.f), 63.f));   // rintf = round-half-even, matches jnp.round
  int py = (int)rintf(fminf(fmaxf(cgy, 0.f), 63.f));
  int xcc[5], ycc[5]; bool mx[5], my[5];
  #pragma unroll
  for (int d = 0; d < 5; d++) {
    int xv = px + d - 2; mx[d] = (xv >= 0 && xv < 64); xcc[d] = min(max(xv, 0), 63);
    int yv = py + d - 2; my[d] = (yv >= 0 && yv < 64); ycc[d] = min(max(yv, 0), 63);
  }
  float pv[25]; float m = -3.4e38f;
  #pragma unroll
  for (int i = 0; i < 5; i++)
    #pragma unroll
    for (int j = 0; j < 5; j++) {
      float v = -3.4e38f;
      if (my[i] && mx[j]) v = hm[ycc[i] * 64 + xcc[j]];
      pv[i * 5 + j] = v; m = fmaxf(m, v);
    }
  float s = 0.f, rx = 0.f, ry = 0.f;
  #pragma unroll
  for (int i = 0; i < 5; i++)
    #pragma unroll
    for (int j = 0; j < 5; j++) {
      float e = (my[i] && mx[j]) ? expf(pv[i * 5 + j] - m) : 0.f;
      s += e; rx += e * (float)xcc[j]; ry += e * (float)ycc[i];
    }
  rx /= s; ry /= s;

  float cx = a * cgx + (1.f - a) * rx;
  float cy = a * cgy + (1.f - a) * ry;

  // bilinear sample of off[b,k,c,:,:] at (cx, cy)
  float ix = fminf(fmaxf(cx, 0.f), 63.f);
  float iy = fminf(fmaxf(cy, 0.f), 63.f);
  float x0f = floorf(ix), y0f = floorf(iy);
  float wx = ix - x0f, wy = iy - y0f;
  int x0 = min(max((int)x0f, 0), 63); int x1 = min(x0 + 1, 63);
  int y0 = min(max((int)y0f, 0), 63); int y1 = min(y0 + 1, 63);
  const float* oc0 = off + (size_t)idx * 2 * HWPIX;
  const float* oc1 = oc0 + HWPIX;
  float v00 = oc0[y0 * 64 + x0], v01 = oc0[y0 * 64 + x1];
  float v10 = oc0[y1 * 64 + x0], v11 = oc0[y1 * 64 + x1];
  float s0 = (1.f - wy) * ((1.f - wx) * v00 + wx * v01) + wy * ((1.f - wx) * v10 + wx * v11);
  v00 = oc1[y0 * 64 + x0]; v01 = oc1[y0 * 64 + x1];
  v10 = oc1[y1 * 64 + x0]; v11 = oc1[y1 * 64 + x1];
  float s1 = (1.f - wy) * ((1.f - wx) * v00 + wx * v01) + wy * ((1.f - wx) * v10 + wx * v11);

  coords_out[idx * 2]     = cx + fw * s0;
  coords_out[idx * 2 + 1] = cy + fw * s1;
}

// ---- output layout (tuple flattened in order) ----
#define HEAT_OFS   0
#define OFF_OFS    2228224
#define VAR_OFS    6684672
#define FW_OFS     8912896
#define COORD_OFS  8912897
#define SCORE_OFS  8913985

#define WT_S1 0
#define WT_S2 1179648
#define WT_H1 2359296
#define WT_O1 3538944
#define WT_V1 4718592

extern "C" void kernel_launch(void* const* d_in, const int* in_sizes, int n_in,
                              void* d_out, int out_size)
{
  const float* x    = (const float*)d_in[0];
  const float* w_s1 = (const float*)d_in[1];
  const float* g_s1 = (const float*)d_in[2];
  const float* b_s1 = (const float*)d_in[3];
  const float* w_s2 = (const float*)d_in[4];
  const float* g_s2 = (const float*)d_in[5];
  const float* b_s2 = (const float*)d_in[6];
  const float* w_h1 = (const float*)d_in[7];
  const float* g_h1 = (const float*)d_in[8];
  const float* b_h1 = (const float*)d_in[9];
  const float* w_h2 = (const float*)d_in[10];
  const float* c_h2 = (const float*)d_in[11];
  const float* w_o1 = (const float*)d_in[12];
  const float* g_o1 = (const float*)d_in[13];
  const float* b_o1 = (const float*)d_in[14];
  const float* w_o2 = (const float*)d_in[15];
  const float* c_o2 = (const float*)d_in[16];
  const float* w_v1 = (const float*)d_in[17];
  const float* g_v1 = (const float*)d_in[18];
  const float* b_v1 = (const float*)d_in[19];
  const float* w_v2 = (const float*)d_in[20];
  const float* c_v2 = (const float*)d_in[21];
  const float* alpha  = (const float*)d_in[22];
  const float* fusion = (const float*)d_in[23];

  float* out    = (float*)d_out;
  float* heat   = out + HEAT_OFS;
  float* offp   = out + OFF_OFS;
  float* varp   = out + VAR_OFS;
  float* fwp    = out + FW_OFS;
  float* coords = out + COORD_OFS;
  float* scores = out + SCORE_OFS;

  void *p1, *p2, *pw, *pcg;
  cudaGetSymbolAddress(&p1, g_buf1);
  cudaGetSymbolAddress(&p2, g_buf2);
  cudaGetSymbolAddress(&pw, g_wt);
  cudaGetSymbolAddress(&pcg, g_cg);
  float* buf1 = (float*)p1;
  float* buf2 = (float*)p2;
  float* wt   = (float*)pw;
  float* cgp  = (float*)pcg;

  // weight transforms (fold BN scale, duplicate for f32x2 lanes)
  wtrans2_kernel<<<(256 * 256 * 9 + 255) / 256, 256>>>(w_s1, g_s1, wt + WT_S1, 256, 256);
  wtrans2_kernel<<<(256 * 256 * 9 + 255) / 256, 256>>>(w_s2, g_s2, wt + WT_S2, 256, 256);
  wtrans2_kernel<<<(256 * 256 * 9 + 255) / 256, 256>>>(w_h1, g_h1, wt + WT_H1, 256, 256);
  wtrans2_kernel<<<(256 * 256 * 9 + 255) / 256, 256>>>(w_o1, g_o1, wt + WT_O1, 256, 256);
  wtrans2_kernel<<<(128 * 256 * 9 + 255) / 256, 256>>>(w_v1, g_v1, wt + WT_V1, 256, 128);

  // stem
  conv3x3_kernel<<<dim3(16, 4, NB), 256>>>(x,    wt + WT_S1, b_s1, buf1, 256, 256);
  conv3x3_kernel<<<dim3(16, 4, NB), 256>>>(buf1, wt + WT_S2, b_s2, buf2, 256, 256);
  // heat branch
  conv3x3_kernel<<<dim3(16, 4, NB), 256>>>(buf2, wt + WT_H1, b_h1, buf1, 256, 256);
  conv1x1_kernel<17><<<dim3(16, NB), 256>>>(buf1, w_h2, c_h2, heat, 256, 0);
  // offset branch
  conv3x3_kernel<<<dim3(16, 4, NB), 256>>>(buf2, wt + WT_O1, b_o1, buf1, 256, 256);
  conv1x1_kernel<34><<<dim3(16, NB), 256>>>(buf1, w_o2, c_o2, offp, 256, 0);
  // var branch
  conv3x3_kernel<<<dim3(16, 2, NB), 256>>>(buf2, wt + WT_V1, b_v1, buf1, 256, 128);
  conv1x1_kernel<17><<<dim3(16, NB), 256>>>(buf1, w_v2, c_v2, varp, 128, 1);
  // epilogue
  softargmax_kernel<<<NB * NK, 256>>>(heat, cgp, scores);
  finalize_kernel<<<3, 256>>>(heat, offp, cgp, alpha, fusion, coords, fwp);

  (void)in_sizes; (void)n_in; (void)out_size;
}

// round 3
// speedup vs baseline: 3.3155x; 3.3155x over previous
#include <cuda_runtime.h>
#include <cuda_bf16.h>
#include <math.h>
#include <stdint.h>

#define NB 32
#define NK 17
#define HWPIX 4096

// ---------------- mma.sync / ldmatrix helpers (sm_80+ PTX, no 'a' features) ----------------
__device__ __forceinline__ uint32_t smem_to_u32(const void* p){
  uint32_t a; asm("{ .reg .u64 t; cvta.to.shared.u64 t, %1; cvt.u32.u64 %0, t; }" : "=r"(a) : "l"(p));
  return a;
}
__device__ __forceinline__ void ldsm4(uint32_t* r, uint32_t a){
  asm volatile("ldmatrix.sync.aligned.m8n8.x4.shared.b16 {%0,%1,%2,%3}, [%4];"
    : "=r"(r[0]), "=r"(r[1]), "=r"(r[2]), "=r"(r[3]) : "r"(a));
}
__device__ __forceinline__ void mma16816(float* d, const uint32_t* a, uint32_t b0, uint32_t b1){
  asm volatile("mma.sync.aligned.m16n8k16.row.col.f32.bf16.bf16.f32 "
    "{%0,%1,%2,%3}, {%4,%5,%6,%7}, {%8,%9}, {%0,%1,%2,%3};"
    : "+f"(d[0]), "+f"(d[1]), "+f"(d[2]), "+f"(d[3])
    : "r"(a[0]), "r"(a[1]), "r"(a[2]), "r"(a[3]), "r"(b0), "r"(b1));
}
__device__ __forceinline__ void cpa16_full(uint32_t d, const void* s){
  asm volatile("cp.async.cg.shared.global [%0], [%1], 16;" :: "r"(d), "l"(s));
}
__device__ __forceinline__ void cpa16z(uint32_t d, const void* s, int n){
  asm volatile("cp.async.cg.shared.global [%0], [%1], 16, %2;" :: "r"(d), "l"(s), "r"(n));
}
#define CP_COMMIT() asm volatile("cp.async.commit_group;" ::: "memory")
#define CP_WAIT(n)  asm volatile("cp.async.wait_group %0;" :: "n"(n) : "memory")
__device__ __forceinline__ uint32_t swz128(uint32_t o){ return o ^ ((o >> 3) & 0x70); }

// ---------------- static scratch ----------------
__device__ __align__(256) __nv_bfloat16 g_nh0[(size_t)NB*HWPIX*256];
__device__ __align__(256) __nv_bfloat16 g_nl0[(size_t)NB*HWPIX*256];
__device__ __align__(256) __nv_bfloat16 g_nh1[(size_t)NB*HWPIX*256];
__device__ __align__(256) __nv_bfloat16 g_nl1[(size_t)NB*HWPIX*256];
__device__ float g_f32[(size_t)NB*256*HWPIX];
// pre-swizzled hi/lo weights: [octile][c=tap*4+icq (36)][128oc x 64ic swizzled 16KB block]
// elem offsets: s1 0 | s2 589824 | h1 1179648 | o1 1769472 | v1 2359296
__device__ __align__(256) __nv_bfloat16 g_awh[2654208];
__device__ __align__(256) __nv_bfloat16 g_awl[2654208];
__device__ float g_cg[NB * NK * 2];

// ---------------- x: NCHW f32 -> NHWC bf16 hi/lo ----------------
__global__ void transpose_split_kernel(const float* __restrict__ x,
                                       __nv_bfloat16* __restrict__ xh,
                                       __nv_bfloat16* __restrict__ xl)
{
  __shared__ float t[64][65];
  int b = blockIdx.z, icb = blockIdx.y, pb = blockIdx.x;
  int p0 = pb << 6, ic0 = icb << 6;
  int tid = threadIdx.x;
  int r = tid >> 6, c = tid & 63;
  const float* xp = x + ((size_t)b * 256 + ic0) * HWPIX + p0;
  #pragma unroll
  for (int k = 0; k < 16; k++) {
    int icl = (k << 2) + r;
    t[icl][c] = xp[(size_t)icl * HWPIX + c];
  }
  __syncthreads();
  #pragma unroll
  for (int k = 0; k < 16; k++) {
    int pl = (k << 2) + r;
    float v = t[c][pl];
    __nv_bfloat16 hi = __float2bfloat16(v);
    __nv_bfloat16 lo = __float2bfloat16(v - __bfloat162float(hi));
    size_t dst = (((size_t)b << 12) + p0 + pl) * 256 + ic0 + c;
    xh[dst] = hi; xl[dst] = lo;
  }
}

// ---------------- weight transform -> pre-swizzled hi/lo A blocks ----------------
__global__ void wtrans_kernel(const float* __restrict__ w, const float* __restrict__ g,
                              __nv_bfloat16* __restrict__ awh, __nv_bfloat16* __restrict__ awl,
                              int n)
{
  int idx = blockIdx.x * 256 + threadIdx.x;
  if (idx >= n) return;
  int icr = idx & 63;
  int ocr = (idx >> 6) & 127;
  int c   = (idx >> 13) % 36;
  int oct = idx / (36 * 8192);
  int t = c >> 2, icq = c & 3;
  int oc = (oct << 7) + ocr;
  int ic = (icq << 6) + icr;
  float val = w[((size_t)(oc * 256 + ic)) * 9 + t] * g[oc] * rsqrtf(1.0f + 1e-5f);
  __nv_bfloat16 hi = __float2bfloat16(val);
  __nv_bfloat16 lo = __float2bfloat16(val - __bfloat162float(hi));
  uint32_t off = (ocr << 7) + (icr << 1);
  uint32_t sw = swz128(off);
  size_t dst = ((size_t)(oct * 36 + c) << 13) + (sw >> 1);
  awh[dst] = hi; awl[dst] = lo;
}

// ---------------- HMMA implicit 3x3 conv + BN(fold) + ReLU ----------------
// CTA: M=128 oc x N=128 px (2 image rows). 8 warps, warp tile m32 x n64.
// K: 4 ic-blocks x 9 taps (taps resolved by shifted ldmatrix addressing in a haloed B tile).
// smem: A stages 2x32KB @0 ; B halo stages 2x67584 @65536. total 200704.
#define A_STAGE 32768
#define B_BASE  65536
#define B_STAGE 67584
#define B_HALF  33792
#define SMEM_CONV 200704

template<int MODE>  // 0: write NHWC bf16 hi/lo (OC=256) ; 1: write NCHW fp32
__global__ void __launch_bounds__(256, 1)
conv3_mma(const __nv_bfloat16* __restrict__ xh, const __nv_bfloat16* __restrict__ xl,
          const __nv_bfloat16* __restrict__ awh, const __nv_bfloat16* __restrict__ awl,
          const float* __restrict__ bias,
          __nv_bfloat16* __restrict__ yh, __nv_bfloat16* __restrict__ yl,
          float* __restrict__ yf, int OC)
{
  extern __shared__ char smem[];
  const uint32_t sb = smem_to_u32(smem);
  const int tid = threadIdx.x, wid = tid >> 5, lane = tid & 31;
  const int lr = lane & 15, lh = lane >> 4;
  const int b = blockIdx.z, oct = blockIdx.y, pt = blockIdx.x;
  const int p0 = pt << 7;          // 128 px per tile
  const int y0 = pt << 1;          // 2 image rows
  const int wM = (wid & 3) << 5;   // warp oc base (0..96)
  const int wN = (wid >> 2) << 6;  // warp px base (0 or 64)

  float acc[2][8][4];
  #pragma unroll
  for (int mt = 0; mt < 2; mt++)
    #pragma unroll
    for (int q = 0; q < 8; q++)
      #pragma unroll
      for (int r = 0; r < 4; r++) acc[mt][q][r] = 0.f;

  // ---- loaders ----
  auto loadA = [&](int c, int buf){
    uint32_t dst = sb + buf * A_STAGE;
    const char* ah = (const char*)(awh + ((size_t)(oct * 36 + c) << 13));
    const char* al = (const char*)(awl + ((size_t)(oct * 36 + c) << 13));
    #pragma unroll
    for (int i = 0; i < 4; i++) {
      int o16 = (tid + (i << 8)) << 4;
      cpa16_full(dst + o16, ah + o16);
      cpa16_full(dst + 16384 + o16, al + o16);
    }
  };
  auto loadB = [&](int icq, int buf){
    uint32_t dst = sb + B_BASE + buf * B_STAGE;
    // halo: 4 rows (y0-1..y0+2) x 66 cols (-1..64), 64 ic bf16 each (128B), swizzled
    #pragma unroll
    for (int i = 0; i < 9; i++) {
      int q = tid + (i << 8);
      if (q < 2112) {
        int sct = q & 7;
        int pr  = q >> 3;          // 0..263
        int hr  = pr / 66, hc = pr % 66;
        int gy = y0 - 1 + hr, gx = hc - 1;
        bool v = ((unsigned)gy < 64u) && ((unsigned)gx < 64u);
        uint32_t dsw = swz128((uint32_t)((pr << 7) + (sct << 4)));
        size_t ge = v ? (((((size_t)b << 12) + (gy << 6) + gx) << 8) + (icq << 6) + (sct << 3)) : 0;
        cpa16z(dst + dsw, xh + ge, v ? 16 : 0);
        cpa16z(dst + B_HALF + dsw, xl + ge, v ? 16 : 0);
      }
    }
  };

  // ---- pipeline ----
  loadB(0, 0);
  loadA(0, 0);
  CP_COMMIT();

  // A-fragment rows are step-invariant
  uint32_t arow[2];
  #pragma unroll
  for (int mt = 0; mt < 2; mt++) arow[mt] = (uint32_t)((wM + (mt << 4) + lr) << 7);

  for (int s = 0; s < 36; s++) {
    const int t = s % 9, icq = s / 9;
    const bool haveNext = (s + 1 < 36);
    if (haveNext) {
      int sn = s + 1;
      loadA((sn % 9) * 4 + (sn / 9), sn & 1);
      if (t == 0 && icq + 1 < 4) loadB(icq + 1, (icq + 1) & 1);
      CP_COMMIT();
    }
    if (haveNext) CP_WAIT(1); else CP_WAIT(0);
    __syncthreads();

    const int dy = t / 3 - 1, dx = t % 3 - 1;
    const uint32_t Ab = sb + (s & 1) * A_STAGE;
    const uint32_t Bb = sb + B_BASE + (icq & 1) * B_STAGE;
    uint32_t brow[4];
    #pragma unroll
    for (int j = 0; j < 4; j++) {
      int p = wN + (j << 4) + lr;
      int hy = (p >> 6) + 1 + dy;
      int hx = (p & 63) + 1 + dx;
      brow[j] = (uint32_t)(((hy * 66 + hx)) << 7);
    }

    #pragma unroll
    for (int ks = 0; ks < 4; ks++) {
      const uint32_t cofs = (uint32_t)(((ks << 1) + lh) << 4);
      uint32_t ah[2][4], al[2][4], bh[4][4], bl[4][4];
      #pragma unroll
      for (int mt = 0; mt < 2; mt++) {
        uint32_t ao = swz128(arow[mt] + cofs);
        ldsm4(ah[mt], Ab + ao);
        ldsm4(al[mt], Ab + 16384 + ao);
      }
      #pragma unroll
      for (int j = 0; j < 4; j++) {
        uint32_t bo = swz128(brow[j] + cofs);
        ldsm4(bh[j], Bb + bo);
        ldsm4(bl[j], Bb + B_HALF + bo);
      }
      #pragma unroll
      for (int mt = 0; mt < 2; mt++)
        #pragma unroll
        for (int j = 0; j < 4; j++)
          #pragma unroll
          for (int f = 0; f < 2; f++) {
            float* d = acc[mt][(j << 1) + f];
            mma16816(d, ah[mt], bh[j][f], bh[j][2 + f]);
            mma16816(d, ah[mt], bl[j][f], bl[j][2 + f]);
            mma16816(d, al[mt], bh[j][f], bh[j][2 + f]);
          }
    }
    __syncthreads();
  }

  // ---- epilogue ----
  if (MODE == 1) {
    // NCHW fp32 direct: d0,d1 are adjacent px
    #pragma unroll
    for (int mt = 0; mt < 2; mt++) {
      int ocl = wM + (mt << 4) + (lane >> 2);
      int oc = (oct << 7) + ocl;
      float b0 = bias[oc], b8 = bias[oc + 8];
      float* base0 = yf + (((size_t)b * OC + oc) << 12) + p0;
      #pragma unroll
      for (int j = 0; j < 4; j++)
        #pragma unroll
        for (int f = 0; f < 2; f++) {
          float* d = acc[mt][(j << 1) + f];
          int colL = wN + (j << 4) + (f << 3) + ((lane & 3) << 1);
          float2 v;
          v.x = fmaxf(d[0] + b0, 0.f); v.y = fmaxf(d[1] + b0, 0.f);
          *(float2*)(base0 + colL) = v;
          v.x = fmaxf(d[2] + b8, 0.f); v.y = fmaxf(d[3] + b8, 0.f);
          *(float2*)(base0 + (8 << 12) + colL) = v;
        }
    }
  } else {
    // smem transpose -> NHWC bf16 hi/lo
    float* sm = (float*)smem;  // [128 px][132]
    #pragma unroll
    for (int mt = 0; mt < 2; mt++) {
      int ocl = wM + (mt << 4) + (lane >> 2);
      float b0 = bias[(oct << 7) + ocl], b8 = bias[(oct << 7) + ocl + 8];
      #pragma unroll
      for (int j = 0; j < 4; j++)
        #pragma unroll
        for (int f = 0; f < 2; f++) {
          float* d = acc[mt][(j << 1) + f];
          int colL = wN + (j << 4) + (f << 3) + ((lane & 3) << 1);
          sm[colL * 132 + ocl]           = fmaxf(d[0] + b0, 0.f);
          sm[(colL + 1) * 132 + ocl]     = fmaxf(d[1] + b0, 0.f);
          sm[colL * 132 + ocl + 8]       = fmaxf(d[2] + b8, 0.f);
          sm[(colL + 1) * 132 + ocl + 8] = fmaxf(d[3] + b8, 0.f);
        }
    }
    __syncthreads();
    int px = tid >> 1, oh = (tid & 1) << 6;
    const float* row = sm + px * 132 + oh;
    size_t gbase = (((size_t)b << 12) + p0 + px) * 256 + (oct << 7) + oh;
    #pragma unroll
    for (int j = 0; j < 64; j += 4) {
      float4 v = *(const float4*)(row + j);
      __nv_bfloat16 h0 = __float2bfloat16(v.x), h1 = __float2bfloat16(v.y);
      __nv_bfloat16 h2 = __float2bfloat16(v.z), h3 = __float2bfloat16(v.w);
      __nv_bfloat16 l0 = __float2bfloat16(v.x - __bfloat162float(h0));
      __nv_bfloat16 l1 = __float2bfloat16(v.y - __bfloat162float(h1));
      __nv_bfloat16 l2 = __float2bfloat16(v.z - __bfloat162float(h2));
      __nv_bfloat16 l3 = __float2bfloat16(v.w - __bfloat162float(h3));
      uint2 hv, lv;
      hv.x = (uint32_t)__bfloat16_as_ushort(h0) | ((uint32_t)__bfloat16_as_ushort(h1) << 16);
      hv.y = (uint32_t)__bfloat16_as_ushort(h2) | ((uint32_t)__bfloat16_as_ushort(h3) << 16);
      lv.x = (uint32_t)__bfloat16_as_ushort(l0) | ((uint32_t)__bfloat16_as_ushort(l1) << 16);
      lv.y = (uint32_t)__bfloat16_as_ushort(l2) | ((uint32_t)__bfloat16_as_ushort(l3) << 16);
      *(uint2*)(yh + gbase + j) = hv;
      *(uint2*)(yl + gbase + j) = lv;
    }
  }
}

// ---------------- 1x1 heads, soft-argmax, finalize (validated in R1) ----------------
__device__ __forceinline__ float softplusf(float x){
  return fmaxf(x, 0.f) + log1pf(expf(-fabsf(x)));
}

template<int OC>
__global__ __launch_bounds__(256)
void conv1x1_kernel(const float* __restrict__ x, const float* __restrict__ w,
                    const float* __restrict__ bias, float* __restrict__ y,
                    int IC, int act)
{
  __shared__ float ws[OC * 256];
  int b = blockIdx.y;
  int tid = threadIdx.x;
  int n = OC * IC;
  for (int q = tid; q < n; q += 256) ws[q] = w[q];
  __syncthreads();
  int pix = blockIdx.x * 256 + tid;
  const float* xp = x + (size_t)b * IC * HWPIX + pix;
  float acc[OC];
  #pragma unroll
  for (int o = 0; o < OC; o++) acc[o] = bias[o];
  for (int ic = 0; ic < IC; ic += 4) {
    float x0 = xp[(size_t)ic * HWPIX];
    float x1 = xp[(size_t)(ic + 1) * HWPIX];
    float x2 = xp[(size_t)(ic + 2) * HWPIX];
    float x3 = xp[(size_t)(ic + 3) * HWPIX];
    #pragma unroll
    for (int o = 0; o < OC; o++) {
      float4 w4 = *(const float4*)&ws[o * IC + ic];
      acc[o] += w4.x * x0 + w4.y * x1 + w4.z * x2 + w4.w * x3;
    }
  }
  float* yp = y + ((size_t)b * OC) * HWPIX + pix;
  #pragma unroll
  for (int o = 0; o < OC; o++) {
    float v = acc[o];
    if (act) v = softplusf(v);
    yp[(size_t)o * HWPIX] = v;
  }
}

__global__ void softargmax_kernel(const float* __restrict__ heat, float* __restrict__ cg,
                                  float* __restrict__ scores)
{
  int bk = blockIdx.x;
  const float* h = heat + (size_t)bk * HWPIX;
  int tid = threadIdx.x;
  __shared__ float r0[256], r1[256], r2[256];

  float m = -3.4e38f;
  for (int i = tid; i < HWPIX; i += 256) m = fmaxf(m, h[i]);
  r0[tid] = m; __syncthreads();
  for (int s = 128; s > 0; s >>= 1) { if (tid < s) r0[tid] = fmaxf(r0[tid], r0[tid + s]); __syncthreads(); }
  float M = r0[0];
  __syncthreads();

  float s = 0.f, sx = 0.f, sy = 0.f;
  for (int i = tid; i < HWPIX; i += 256) {
    float e = expf(h[i] - M);
    s += e; sx += e * (float)(i & 63); sy += e * (float)(i >> 6);
  }
  r0[tid] = s; r1[tid] = sx; r2[tid] = sy; __syncthreads();
  for (int st = 128; st > 0; st >>= 1) {
    if (tid < st) { r0[tid] += r0[tid + st]; r1[tid] += r1[tid + st]; r2[tid] += r2[tid + st]; }
    __syncthreads();
  }
  if (tid == 0) {
    cg[bk * 2]     = r1[0] / r0[0];
    cg[bk * 2 + 1] = r2[0] / r0[0];
    scores[bk] = M;
  }
}

__global__ void finalize_kernel(const float* __restrict__ heat, const float* __restrict__ off,
                                const float* __restrict__ cg, const float* __restrict__ alpha_p,
                                const float* __restrict__ fusion_p, float* __restrict__ coords_out,
                                float* __restrict__ fw_out)
{
  int idx = blockIdx.x * blockDim.x + threadIdx.x;
  float fw = 1.f / (1.f + expf(-fusion_p[0]));
  if (idx == 0) fw_out[0] = fw;
  if (idx >= NB * NK) return;
  float a = 1.f / (1.f + expf(-alpha_p[0]));
  float cgx = cg[idx * 2], cgy = cg[idx * 2 + 1];
  const float* hm = heat + (size_t)idx * HWPIX;

  int px = (int)rintf(fminf(fmaxf(cgx, 0.f), 63.f));
  int py = (int)rintf(fminf(fmaxf(cgy, 0.f), 63.f));
  int xcc[5], ycc[5]; bool mx[5], my[5];
  #pragma unroll
  for (int d = 0; d < 5; d++) {
    int xv = px + d - 2; mx[d] = (xv >= 0 && xv < 64); xcc[d] = min(max(xv, 0), 63);
    int yv = py + d - 2; my[d] = (yv >= 0 && yv < 64); ycc[d] = min(max(yv, 0), 63);
  }
  float pv[25]; float m = -3.4e38f;
  #pragma unroll
  for (int i = 0; i < 5; i++)
    #pragma unroll
    for (int j = 0; j < 5; j++) {
      float v = -3.4e38f;
      if (my[i] && mx[j]) v = hm[ycc[i] * 64 + xcc[j]];
      pv[i * 5 + j] = v; m = fmaxf(m, v);
    }
  float s = 0.f, rx = 0.f, ry = 0.f;
  #pragma unroll
  for (int i = 0; i < 5; i++)
    #pragma unroll
    for (int j = 0; j < 5; j++) {
      float e = (my[i] && mx[j]) ? expf(pv[i * 5 + j] - m) : 0.f;
      s += e; rx += e * (float)xcc[j]; ry += e * (float)ycc[i];
    }
  rx /= s; ry /= s;

  float cx = a * cgx + (1.f - a) * rx;
  float cy = a * cgy + (1.f - a) * ry;

  float ix = fminf(fmaxf(cx, 0.f), 63.f);
  float iy = fminf(fmaxf(cy, 0.f), 63.f);
  float x0f = floorf(ix), y0f = floorf(iy);
  float wx = ix - x0f, wy = iy - y0f;
  int x0 = min(max((int)x0f, 0), 63); int x1 = min(x0 + 1, 63);
  int y0 = min(max((int)y0f, 0), 63); int y1 = min(y0 + 1, 63);
  const float* oc0 = off + (size_t)idx * 2 * HWPIX;
  const float* oc1 = oc0 + HWPIX;
  float v00 = oc0[y0 * 64 + x0], v01 = oc0[y0 * 64 + x1];
  float v10 = oc0[y1 * 64 + x0], v11 = oc0[y1 * 64 + x1];
  float s0 = (1.f - wy) * ((1.f - wx) * v00 + wx * v01) + wy * ((1.f - wx) * v10 + wx * v11);
  v00 = oc1[y0 * 64 + x0]; v01 = oc1[y0 * 64 + x1];
  v10 = oc1[y1 * 64 + x0]; v11 = oc1[y1 * 64 + x1];
  float s1 = (1.f - wy) * ((1.f - wx) * v00 + wx * v01) + wy * ((1.f - wx) * v10 + wx * v11);

  coords_out[idx * 2]     = cx + fw * s0;
  coords_out[idx * 2 + 1] = cy + fw * s1;
}

// ---------------- output layout ----------------
#define HEAT_OFS   0
#define OFF_OFS    2228224
#define VAR_OFS    6684672
#define FW_OFS     8912896
#define COORD_OFS  8912897
#define SCORE_OFS  8913985

#define AW_S1 0
#define AW_S2 589824
#define AW_H1 1179648
#define AW_O1 1769472
#define AW_V1 2359296

extern "C" void kernel_launch(void* const* d_in, const int* in_sizes, int n_in,
                              void* d_out, int out_size)
{
  const float* x    = (const float*)d_in[0];
  const float* w_s1 = (const float*)d_in[1];
  const float* g_s1 = (const float*)d_in[2];
  const float* b_s1 = (const float*)d_in[3];
  const float* w_s2 = (const float*)d_in[4];
  const float* g_s2 = (const float*)d_in[5];
  const float* b_s2 = (const float*)d_in[6];
  const float* w_h1 = (const float*)d_in[7];
  const float* g_h1 = (const float*)d_in[8];
  const float* b_h1 = (const float*)d_in[9];
  const float* w_h2 = (const float*)d_in[10];
  const float* c_h2 = (const float*)d_in[11];
  const float* w_o1 = (const float*)d_in[12];
  const float* g_o1 = (const float*)d_in[13];
  const float* b_o1 = (const float*)d_in[14];
  const float* w_o2 = (const float*)d_in[15];
  const float* c_o2 = (const float*)d_in[16];
  const float* w_v1 = (const float*)d_in[17];
  const float* g_v1 = (const float*)d_in[18];
  const float* b_v1 = (const float*)d_in[19];
  const float* w_v2 = (const float*)d_in[20];
  const float* c_v2 = (const float*)d_in[21];
  const float* alpha  = (const float*)d_in[22];
  const float* fusion = (const float*)d_in[23];

  float* out    = (float*)d_out;
  float* heat   = out + HEAT_OFS;
  float* offp   = out + OFF_OFS;
  float* varp   = out + VAR_OFS;
  float* fwp    = out + FW_OFS;
  float* coords = out + COORD_OFS;
  float* scores = out + SCORE_OFS;

  void *ph0, *pl0, *ph1, *pl1, *pf, *pwh, *pwl, *pcg;
  cudaGetSymbolAddress(&ph0, g_nh0);
  cudaGetSymbolAddress(&pl0, g_nl0);
  cudaGetSymbolAddress(&ph1, g_nh1);
  cudaGetSymbolAddress(&pl1, g_nl1);
  cudaGetSymbolAddress(&pf,  g_f32);
  cudaGetSymbolAddress(&pwh, g_awh);
  cudaGetSymbolAddress(&pwl, g_awl);
  cudaGetSymbolAddress(&pcg, g_cg);
  __nv_bfloat16* Ah = (__nv_bfloat16*)ph0;
  __nv_bfloat16* Al = (__nv_bfloat16*)pl0;
  __nv_bfloat16* Bh = (__nv_bfloat16*)ph1;
  __nv_bfloat16* Bl = (__nv_bfloat16*)pl1;
  float* F32 = (float*)pf;
  __nv_bfloat16* awh = (__nv_bfloat16*)pwh;
  __nv_bfloat16* awl = (__nv_bfloat16*)pwl;
  float* cgp = (float*)pcg;

  cudaFuncSetAttribute(conv3_mma<0>, cudaFuncAttributeMaxDynamicSharedMemorySize, SMEM_CONV);
  cudaFuncSetAttribute(conv3_mma<1>, cudaFuncAttributeMaxDynamicSharedMemorySize, SMEM_CONV);

  transpose_split_kernel<<<dim3(64, 4, NB), 256>>>(x, Ah, Al);
  wtrans_kernel<<<2304, 256>>>(w_s1, g_s1, awh + AW_S1, awl + AW_S1, 589824);
  wtrans_kernel<<<2304, 256>>>(w_s2, g_s2, awh + AW_S2, awl + AW_S2, 589824);
  wtrans_kernel<<<2304, 256>>>(w_h1, g_h1, awh + AW_H1, awl + AW_H1, 589824);
  wtrans_kernel<<<2304, 256>>>(w_o1, g_o1, awh + AW_O1, awl + AW_O1, 589824);
  wtrans_kernel<<<1152, 256>>>(w_v1, g_v1, awh + AW_V1, awl + AW_V1, 294912);

  // stem: x(A) -> s1(B) -> s2(A)
  conv3_mma<0><<<dim3(32, 2, NB), 256, SMEM_CONV>>>(Ah, Al, awh + AW_S1, awl + AW_S1, b_s1, Bh, Bl, nullptr, 256);
  conv3_mma<0><<<dim3(32, 2, NB), 256, SMEM_CONV>>>(Bh, Bl, awh + AW_S2, awl + AW_S2, b_s2, Ah, Al, nullptr, 256);

  // heat branch
  conv3_mma<1><<<dim3(32, 2, NB), 256, SMEM_CONV>>>(Ah, Al, awh + AW_H1, awl + AW_H1, b_h1, nullptr, nullptr, F32, 256);
  conv1x1_kernel<17><<<dim3(16, NB), 256>>>(F32, w_h2, c_h2, heat, 256, 0);
  // offset branch
  conv3_mma<1><<<dim3(32, 2, NB), 256, SMEM_CONV>>>(Ah, Al, awh + AW_O1, awl + AW_O1, b_o1, nullptr, nullptr, F32, 256);
  conv1x1_kernel<34><<<dim3(16, NB), 256>>>(F32, w_o2, c_o2, offp, 256, 0);
  // var branch
  conv3_mma<1><<<dim3(32, 1, NB), 256, SMEM_CONV>>>(Ah, Al, awh + AW_V1, awl + AW_V1, b_v1, nullptr, nullptr, F32, 128);
  conv1x1_kernel<17><<<dim3(16, NB), 256>>>(F32, w_v2, c_v2, varp, 128, 1);

  // epilogue
  softargmax_kernel<<<NB * NK, 256>>>(heat, cgp, scores);
  finalize_kernel<<<3, 256>>>(heat, offp, cgp, alpha, fusion, coords, fwp);

  (void)in_sizes; (void)n_in; (void)out_size;
}

// round 4
// speedup vs baseline: 3.3375x; 1.0066x over previous
#include <cuda_runtime.h>
#include <cuda_bf16.h>
#include <math.h>
#include <stdint.h>

#define NB 32
#define NK 17
#define HWPIX 4096

// ---------------- mma.sync / ldmatrix helpers ----------------
__device__ __forceinline__ uint32_t smem_to_u32(const void* p){
  uint32_t a; asm("{ .reg .u64 t; cvta.to.shared.u64 t, %1; cvt.u32.u64 %0, t; }" : "=r"(a) : "l"(p));
  return a;
}
__device__ __forceinline__ void ldsm4(uint32_t* r, uint32_t a){
  asm volatile("ldmatrix.sync.aligned.m8n8.x4.shared.b16 {%0,%1,%2,%3}, [%4];"
    : "=r"(r[0]), "=r"(r[1]), "=r"(r[2]), "=r"(r[3]) : "r"(a));
}
__device__ __forceinline__ void mma16816(float* d, const uint32_t* a, uint32_t b0, uint32_t b1){
  asm volatile("mma.sync.aligned.m16n8k16.row.col.f32.bf16.bf16.f32 "
    "{%0,%1,%2,%3}, {%4,%5,%6,%7}, {%8,%9}, {%0,%1,%2,%3};"
    : "+f"(d[0]), "+f"(d[1]), "+f"(d[2]), "+f"(d[3])
    : "r"(a[0]), "r"(a[1]), "r"(a[2]), "r"(a[3]), "r"(b0), "r"(b1));
}
__device__ __forceinline__ void cpa16_full(uint32_t d, const void* s){
  asm volatile("cp.async.cg.shared.global [%0], [%1], 16;" :: "r"(d), "l"(s));
}
__device__ __forceinline__ void cpa16z(uint32_t d, const void* s, int n){
  asm volatile("cp.async.cg.shared.global [%0], [%1], 16, %2;" :: "r"(d), "l"(s), "r"(n));
}
#define CP_COMMIT() asm volatile("cp.async.commit_group;" ::: "memory")
#define CP_WAIT(n)  asm volatile("cp.async.wait_group %0;" :: "n"(n) : "memory")
__device__ __forceinline__ uint32_t swz64(uint32_t o){ return o ^ ((o >> 3) & 0x30); }

// ---------------- static scratch ----------------
__device__ __align__(256) __nv_bfloat16 g_nh0[(size_t)NB*HWPIX*256];
__device__ __align__(256) __nv_bfloat16 g_nl0[(size_t)NB*HWPIX*256];
__device__ __align__(256) __nv_bfloat16 g_nh1[(size_t)NB*HWPIX*256];
__device__ __align__(256) __nv_bfloat16 g_nl1[(size_t)NB*HWPIX*256];
__device__ float g_f32[(size_t)NB*256*HWPIX];
// pre-swizzled hi/lo weights: [oct][c = t*8+icq (72)][128oc x 32ic, 64B rows, SW64, 8KB]
// elem offsets: s1 0 | s2 589824 | h1 1179648 | o1 1769472 | v1 2359296
__device__ __align__(256) __nv_bfloat16 g_awh[2654208];
__device__ __align__(256) __nv_bfloat16 g_awl[2654208];
__device__ float g_cg[NB * NK * 2];

// ---------------- x: NCHW f32 -> NHWC bf16 hi/lo ----------------
__global__ void transpose_split_kernel(const float* __restrict__ x,
                                       __nv_bfloat16* __restrict__ xh,
                                       __nv_bfloat16* __restrict__ xl)
{
  __shared__ float t[64][65];
  int b = blockIdx.z, icb = blockIdx.y, pb = blockIdx.x;
  int p0 = pb << 6, ic0 = icb << 6;
  int tid = threadIdx.x;
  int r = tid >> 6, c = tid & 63;
  const float* xp = x + ((size_t)b * 256 + ic0) * HWPIX + p0;
  #pragma unroll
  for (int k = 0; k < 16; k++) {
    int icl = (k << 2) + r;
    t[icl][c] = xp[(size_t)icl * HWPIX + c];
  }
  __syncthreads();
  #pragma unroll
  for (int k = 0; k < 16; k++) {
    int pl = (k << 2) + r;
    float v = t[c][pl];
    __nv_bfloat16 hi = __float2bfloat16(v);
    __nv_bfloat16 lo = __float2bfloat16(v - __bfloat162float(hi));
    size_t dst = (((size_t)b << 12) + p0 + pl) * 256 + ic0 + c;
    xh[dst] = hi; xl[dst] = lo;
  }
}

// ---------------- weight transform -> pre-swizzled SW64 hi/lo A chunks ----------------
// chunk c = t*8+icq : [128 oc rows][32 ic] 64B rows, swz64, 4096 elems (8KB) per half
__global__ void wtrans_kernel(const float* __restrict__ w, const float* __restrict__ g,
                              __nv_bfloat16* __restrict__ awh, __nv_bfloat16* __restrict__ awl,
                              int n)
{
  int idx = blockIdx.x * 256 + threadIdx.x;
  if (idx >= n) return;
  int icr = idx & 31;
  int ocr = (idx >> 5) & 127;
  int c   = (idx >> 12) % 72;
  int oct = idx / 294912;
  int t = c >> 3, icq = c & 7;
  int oc = (oct << 7) + ocr;
  int ic = (icq << 5) + icr;
  float val = w[((size_t)(oc * 256 + ic)) * 9 + t] * g[oc] * rsqrtf(1.0f + 1e-5f);
  __nv_bfloat16 hi = __float2bfloat16(val);
  __nv_bfloat16 lo = __float2bfloat16(val - __bfloat162float(hi));
  uint32_t off = (ocr << 6) + (icr << 1);
  uint32_t sw = swz64(off);
  size_t dst = ((size_t)(oct * 72 + c) << 12) + (sw >> 1);
  awh[dst] = hi; awl[dst] = lo;
}

// ---------------- HMMA implicit 3x3 conv + BN(fold) + ReLU ----------------
// CTA: M=128 oc x N=256 px (4 image rows), 512 threads / 16 warps, warp tile m32 x n64.
// K: 8 ic-chunks(32) x 9 taps = 72 steps; taps via shifted ldmatrix into haloed B tile.
// smem: A 2x16KB @0 ; B 2x50688 @32768 (hi 25344 + lo 25344 per stage). Both double-buffered.
#define A_STAGE 16384
#define B_BASE  32768
#define B_STAGE 50688
#define B_HALF  25344
#define SMEM_CONV 135168   // epilogue transpose needs 256*132*4

template<int MODE>  // 0: write NHWC bf16 hi/lo (OC=256) ; 1: write NCHW fp32
__global__ void __launch_bounds__(512, 1)
conv3_mma(const __nv_bfloat16* __restrict__ xh, const __nv_bfloat16* __restrict__ xl,
          const __nv_bfloat16* __restrict__ awh, const __nv_bfloat16* __restrict__ awl,
          const float* __restrict__ bias,
          __nv_bfloat16* __restrict__ yh, __nv_bfloat16* __restrict__ yl,
          float* __restrict__ yf, int OC)
{
  extern __shared__ char smem[];
  const uint32_t sb = smem_to_u32(smem);
  const int tid = threadIdx.x, wid = tid >> 5, lane = tid & 31;
  const int lr = lane & 15, lh = lane >> 4;
  const int b = blockIdx.z, oct = blockIdx.y, pt = blockIdx.x;
  const int p0 = pt << 8;          // 256 px per tile
  const int y0 = pt << 2;          // 4 image rows
  const int wM = (wid & 3) << 5;   // warp oc base (0..96)
  const int wN = (wid >> 2) << 6;  // warp px base (0,64,128,192)

  float acc[2][8][4];
  #pragma unroll
  for (int mt = 0; mt < 2; mt++)
    #pragma unroll
    for (int q = 0; q < 8; q++)
      #pragma unroll
      for (int r = 0; r < 4; r++) acc[mt][q][r] = 0.f;

  auto loadA = [&](int c, int buf){
    uint32_t dst = sb + buf * A_STAGE;
    const char* ah = (const char*)(awh + ((size_t)(oct * 72 + c) << 12));
    const char* al = (const char*)(awl + ((size_t)(oct * 72 + c) << 12));
    int o16 = tid << 4;   // 512 thr x 16B = 8192 = one half-chunk
    cpa16_full(dst + o16, ah + o16);
    cpa16_full(dst + 8192 + o16, al + o16);
  };
  auto loadB = [&](int icq, int buf){
    uint32_t dst = sb + B_BASE + buf * B_STAGE;
    // halo: 6 rows (y0-1..y0+4) x 66 cols (-1..64); each row 32 ic = 64B, SW64
    #pragma unroll
    for (int i = 0; i < 4; i++) {
      int q = tid + (i << 9);
      if (q < 1584) {               // 396 rows x 4 sectors
        int sct = q & 3;
        int pr  = q >> 2;           // 0..395
        int hr  = pr / 66, hc = pr % 66;
        int gy = y0 - 1 + hr, gx = hc - 1;
        bool v = ((unsigned)gy < 64u) && ((unsigned)gx < 64u);
        uint32_t dsw = swz64((uint32_t)((pr << 6) + (sct << 4)));
        size_t ge = v ? (((((size_t)b << 12) + (gy << 6) + gx) << 8) + (icq << 5) + (sct << 3)) : 0;
        cpa16z(dst + dsw, xh + ge, v ? 16 : 0);
        cpa16z(dst + B_HALF + dsw, xl + ge, v ? 16 : 0);
      }
    }
  };

  loadB(0, 0);
  loadA(0, 0);
  CP_COMMIT();

  uint32_t arow[2];
  #pragma unroll
  for (int mt = 0; mt < 2; mt++) arow[mt] = (uint32_t)((wM + (mt << 4) + lr) << 6);

  for (int icq = 0; icq < 8; icq++) {
    #pragma unroll 1
    for (int t = 0; t < 9; t++) {
      const int s = icq * 9 + t;
      CP_WAIT(0);
      __syncthreads();
      // issue prefetch for s+1 (overlaps this step's MMAs)
      if (s + 1 < 72) {
        int tn = t + 1, icqn = icq;
        if (tn == 9) { tn = 0; icqn = icq + 1; }
        loadA(tn * 8 + icqn, (s + 1) & 1);
        if (tn == 0) loadB(icqn, icqn & 1);
        CP_COMMIT();
      }

      const int dy = t / 3 - 1, dx = t % 3 - 1;
      const uint32_t Ab = sb + (s & 1) * A_STAGE;
      const uint32_t Bb = sb + B_BASE + (icq & 1) * B_STAGE;
      uint32_t brow[4];
      #pragma unroll
      for (int j = 0; j < 4; j++) {
        int p = wN + (j << 4) + lr;
        int hy = (p >> 6) + 1 + dy;
        int hx = (p & 63) + 1 + dx;
        brow[j] = (uint32_t)((hy * 66 + hx) << 6);
      }

      #pragma unroll
      for (int ks = 0; ks < 2; ks++) {
        const uint32_t cofs = (uint32_t)(((ks << 1) + lh) << 4);
        uint32_t ah[2][4], al[2][4], bh[4][4], bl[4][4];
        #pragma unroll
        for (int mt = 0; mt < 2; mt++) {
          uint32_t ao = swz64(arow[mt] + cofs);
          ldsm4(ah[mt], Ab + ao);
          ldsm4(al[mt], Ab + 8192 + ao);
        }
        #pragma unroll
        for (int j = 0; j < 4; j++) {
          uint32_t bo = swz64(brow[j] + cofs);
          ldsm4(bh[j], Bb + bo);
          ldsm4(bl[j], Bb + B_HALF + bo);
        }
        // term 1: hh   (terms separated so each acc's 3 MMAs have 16 indep MMAs between)
        #pragma unroll
        for (int mt = 0; mt < 2; mt++)
          #pragma unroll
          for (int j = 0; j < 4; j++)
            #pragma unroll
            for (int f = 0; f < 2; f++)
              mma16816(acc[mt][(j << 1) + f], ah[mt], bh[j][f], bh[j][2 + f]);
        // term 2: h*blo
        #pragma unroll
        for (int mt = 0; mt < 2; mt++)
          #pragma unroll
          for (int j = 0; j < 4; j++)
            #pragma unroll
            for (int f = 0; f < 2; f++)
              mma16816(acc[mt][(j << 1) + f], ah[mt], bl[j][f], bl[j][2 + f]);
        // term 3: alo*bh
        #pragma unroll
        for (int mt = 0; mt < 2; mt++)
          #pragma unroll
          for (int j = 0; j < 4; j++)
            #pragma unroll
            for (int f = 0; f < 2; f++)
              mma16816(acc[mt][(j << 1) + f], al[mt], bh[j][f], bh[j][2 + f]);
      }
    }
  }
  __syncthreads();

  // ---- epilogue ----
  if (MODE == 1) {
    #pragma unroll
    for (int mt = 0; mt < 2; mt++) {
      int ocl = wM + (mt << 4) + (lane >> 2);
      int oc = (oct << 7) + ocl;
      float b0 = bias[oc], b8 = bias[oc + 8];
      float* base0 = yf + (((size_t)b * OC + oc) << 12) + p0;
      #pragma unroll
      for (int j = 0; j < 4; j++)
        #pragma unroll
        for (int f = 0; f < 2; f++) {
          float* d = acc[mt][(j << 1) + f];
          int colL = wN + (j << 4) + (f << 3) + ((lane & 3) << 1);
          float2 v;
          v.x = fmaxf(d[0] + b0, 0.f); v.y = fmaxf(d[1] + b0, 0.f);
          *(float2*)(base0 + colL) = v;
          v.x = fmaxf(d[2] + b8, 0.f); v.y = fmaxf(d[3] + b8, 0.f);
          *(float2*)(base0 + (8 << 12) + colL) = v;
        }
    }
  } else {
    float* sm = (float*)smem;  // [256 px][132]
    #pragma unroll
    for (int mt = 0; mt < 2; mt++) {
      int ocl = wM + (mt << 4) + (lane >> 2);
      float b0 = bias[(oct << 7) + ocl], b8 = bias[(oct << 7) + ocl + 8];
      #pragma unroll
      for (int j = 0; j < 4; j++)
        #pragma unroll
        for (int f = 0; f < 2; f++) {
          float* d = acc[mt][(j << 1) + f];
          int colL = wN + (j << 4) + (f << 3) + ((lane & 3) << 1);
          sm[colL * 132 + ocl]           = fmaxf(d[0] + b0, 0.f);
          sm[(colL + 1) * 132 + ocl]     = fmaxf(d[1] + b0, 0.f);
          sm[colL * 132 + ocl + 8]       = fmaxf(d[2] + b8, 0.f);
          sm[(colL + 1) * 132 + ocl + 8] = fmaxf(d[3] + b8, 0.f);
        }
    }
    __syncthreads();
    int px = tid >> 1, oh = (tid & 1) << 6;
    const float* row = sm + px * 132 + oh;
    size_t gbase = (((size_t)b << 12) + p0 + px) * 256 + (oct << 7) + oh;
    #pragma unroll
    for (int j = 0; j < 64; j += 4) {
      float4 v = *(const float4*)(row + j);
      __nv_bfloat16 h0 = __float2bfloat16(v.x), h1 = __float2bfloat16(v.y);
      __nv_bfloat16 h2 = __float2bfloat16(v.z), h3 = __float2bfloat16(v.w);
      __nv_bfloat16 l0 = __float2bfloat16(v.x - __bfloat162float(h0));
      __nv_bfloat16 l1 = __float2bfloat16(v.y - __bfloat162float(h1));
      __nv_bfloat16 l2 = __float2bfloat16(v.z - __bfloat162float(h2));
      __nv_bfloat16 l3 = __float2bfloat16(v.w - __bfloat162float(h3));
      uint2 hv, lv;
      hv.x = (uint32_t)__bfloat16_as_ushort(h0) | ((uint32_t)__bfloat16_as_ushort(h1) << 16);
      hv.y = (uint32_t)__bfloat16_as_ushort(h2) | ((uint32_t)__bfloat16_as_ushort(h3) << 16);
      lv.x = (uint32_t)__bfloat16_as_ushort(l0) | ((uint32_t)__bfloat16_as_ushort(l1) << 16);
      lv.y = (uint32_t)__bfloat16_as_ushort(l2) | ((uint32_t)__bfloat16_as_ushort(l3) << 16);
      *(uint2*)(yh + gbase + j) = hv;
      *(uint2*)(yl + gbase + j) = lv;
    }
  }
}

// ---------------- 1x1 heads, soft-argmax, finalize (validated) ----------------
__device__ __forceinline__ float softplusf(float x){
  return fmaxf(x, 0.f) + log1pf(expf(-fabsf(x)));
}

template<int OC>
__global__ __launch_bounds__(256)
void conv1x1_kernel(const float* __restrict__ x, const float* __restrict__ w,
                    const float* __restrict__ bias, float* __restrict__ y,
                    int IC, int act)
{
  __shared__ float ws[OC * 256];
  int b = blockIdx.y;
  int tid = threadIdx.x;
  int n = OC * IC;
  for (int q = tid; q < n; q += 256) ws[q] = w[q];
  __syncthreads();
  int pix = blockIdx.x * 256 + tid;
  const float* xp = x + (size_t)b * IC * HWPIX + pix;
  float acc[OC];
  #pragma unroll
  for (int o = 0; o < OC; o++) acc[o] = bias[o];
  for (int ic = 0; ic < IC; ic += 4) {
    float x0 = xp[(size_t)ic * HWPIX];
    float x1 = xp[(size_t)(ic + 1) * HWPIX];
    float x2 = xp[(size_t)(ic + 2) * HWPIX];
    float x3 = xp[(size_t)(ic + 3) * HWPIX];
    #pragma unroll
    for (int o = 0; o < OC; o++) {
      float4 w4 = *(const float4*)&ws[o * IC + ic];
      acc[o] += w4.x * x0 + w4.y * x1 + w4.z * x2 + w4.w * x3;
    }
  }
  float* yp = y + ((size_t)b * OC) * HWPIX + pix;
  #pragma unroll
  for (int o = 0; o < OC; o++) {
    float v = acc[o];
    if (act) v = softplusf(v);
    yp[(size_t)o * HWPIX] = v;
  }
}

__global__ void softargmax_kernel(const float* __restrict__ heat, float* __restrict__ cg,
                                  float* __restrict__ scores)
{
  int bk = blockIdx.x;
  const float* h = heat + (size_t)bk * HWPIX;
  int tid = threadIdx.x;
  __shared__ float r0[256], r1[256], r2[256];

  float m = -3.4e38f;
  for (int i = tid; i < HWPIX; i += 256) m = fmaxf(m, h[i]);
  r0[tid] = m; __syncthreads();
  for (int s = 128; s > 0; s >>= 1) { if (tid < s) r0[tid] = fmaxf(r0[tid], r0[tid + s]); __syncthreads(); }
  float M = r0[0];
  __syncthreads();

  float s = 0.f, sx = 0.f, sy = 0.f;
  for (int i = tid; i < HWPIX; i += 256) {
    float e = expf(h[i] - M);
    s += e; sx += e * (float)(i & 63); sy += e * (float)(i >> 6);
  }
  r0[tid] = s; r1[tid] = sx; r2[tid] = sy; __syncthreads();
  for (int st = 128; st > 0; st >>= 1) {
    if (tid < st) { r0[tid] += r0[tid + st]; r1[tid] += r1[tid + st]; r2[tid] += r2[tid + st]; }
    __syncthreads();
  }
  if (tid == 0) {
    cg[bk * 2]     = r1[0] / r0[0];
    cg[bk * 2 + 1] = r2[0] / r0[0];
    scores[bk] = M;
  }
}

__global__ void finalize_kernel(const float* __restrict__ heat, const float* __restrict__ off,
                                const float* __restrict__ cg, const float* __restrict__ alpha_p,
                                const float* __restrict__ fusion_p, float* __restrict__ coords_out,
                                float* __restrict__ fw_out)
{
  int idx = blockIdx.x * blockDim.x + threadIdx.x;
  float fw = 1.f / (1.f + expf(-fusion_p[0]));
  if (idx == 0) fw_out[0] = fw;
  if (idx >= NB * NK) return;
  float a = 1.f / (1.f + expf(-alpha_p[0]));
  float cgx = cg[idx * 2], cgy = cg[idx * 2 + 1];
  const float* hm = heat + (size_t)idx * HWPIX;

  int px = (int)rintf(fminf(fmaxf(cgx, 0.f), 63.f));
  int py = (int)rintf(fminf(fmaxf(cgy, 0.f), 63.f));
  int xcc[5], ycc[5]; bool mx[5], my[5];
  #pragma unroll
  for (int d = 0; d < 5; d++) {
    int xv = px + d - 2; mx[d] = (xv >= 0 && xv < 64); xcc[d] = min(max(xv, 0), 63);
    int yv = py + d - 2; my[d] = (yv >= 0 && yv < 64); ycc[d] = min(max(yv, 0), 63);
  }
  float pv[25]; float m = -3.4e38f;
  #pragma unroll
  for (int i = 0; i < 5; i++)
    #pragma unroll
    for (int j = 0; j < 5; j++) {
      float v = -3.4e38f;
      if (my[i] && mx[j]) v = hm[ycc[i] * 64 + xcc[j]];
      pv[i * 5 + j] = v; m = fmaxf(m, v);
    }
  float s = 0.f, rx = 0.f, ry = 0.f;
  #pragma unroll
  for (int i = 0; i < 5; i++)
    #pragma unroll
    for (int j = 0; j < 5; j++) {
      float e = (my[i] && mx[j]) ? expf(pv[i * 5 + j] - m) : 0.f;
      s += e; rx += e * (float)xcc[j]; ry += e * (float)ycc[i];
    }
  rx /= s; ry /= s;

  float cx = a * cgx + (1.f - a) * rx;
  float cy = a * cgy + (1.f - a) * ry;

  float ix = fminf(fmaxf(cx, 0.f), 63.f);
  float iy = fminf(fmaxf(cy, 0.f), 63.f);
  float x0f = floorf(ix), y0f = floorf(iy);
  float wx = ix - x0f, wy = iy - y0f;
  int x0 = min(max((int)x0f, 0), 63); int x1 = min(x0 + 1, 63);
  int y0 = min(max((int)y0f, 0), 63); int y1 = min(y0 + 1, 63);
  const float* oc0 = off + (size_t)idx * 2 * HWPIX;
  const float* oc1 = oc0 + HWPIX;
  float v00 = oc0[y0 * 64 + x0], v01 = oc0[y0 * 64 + x1];
  float v10 = oc0[y1 * 64 + x0], v11 = oc0[y1 * 64 + x1];
  float s0 = (1.f - wy) * ((1.f - wx) * v00 + wx * v01) + wy * ((1.f - wx) * v10 + wx * v11);
  v00 = oc1[y0 * 64 + x0]; v01 = oc1[y0 * 64 + x1];
  v10 = oc1[y1 * 64 + x0]; v11 = oc1[y1 * 64 + x1];
  float s1 = (1.f - wy) * ((1.f - wx) * v00 + wx * v01) + wy * ((1.f - wx) * v10 + wx * v11);

  coords_out[idx * 2]     = cx + fw * s0;
  coords_out[idx * 2 + 1] = cy + fw * s1;
}

// ---------------- output layout ----------------
#define HEAT_OFS   0
#define OFF_OFS    2228224
#define VAR_OFS    6684672
#define FW_OFS     8912896
#define COORD_OFS  8912897
#define SCORE_OFS  8913985

#define AW_S1 0
#define AW_S2 589824
#define AW_H1 1179648
#define AW_O1 1769472
#define AW_V1 2359296

extern "C" void kernel_launch(void* const* d_in, const int* in_sizes, int n_in,
                              void* d_out, int out_size)
{
  const float* x    = (const float*)d_in[0];
  const float* w_s1 = (const float*)d_in[1];
  const float* g_s1 = (const float*)d_in[2];
  const float* b_s1 = (const float*)d_in[3];
  const float* w_s2 = (const float*)d_in[4];
  const float* g_s2 = (const float*)d_in[5];
  const float* b_s2 = (const float*)d_in[6];
  const float* w_h1 = (const float*)d_in[7];
  const float* g_h1 = (const float*)d_in[8];
  const float* b_h1 = (const float*)d_in[9];
  const float* w_h2 = (const float*)d_in[10];
  const float* c_h2 = (const float*)d_in[11];
  const float* w_o1 = (const float*)d_in[12];
  const float* g_o1 = (const float*)d_in[13];
  const float* b_o1 = (const float*)d_in[14];
  const float* w_o2 = (const float*)d_in[15];
  const float* c_o2 = (const float*)d_in[16];
  const float* w_v1 = (const float*)d_in[17];
  const float* g_v1 = (const float*)d_in[18];
  const float* b_v1 = (const float*)d_in[19];
  const float* w_v2 = (const float*)d_in[20];
  const float* c_v2 = (const float*)d_in[21];
  const float* alpha  = (const float*)d_in[22];
  const float* fusion = (const float*)d_in[23];

  float* out    = (float*)d_out;
  float* heat   = out + HEAT_OFS;
  float* offp   = out + OFF_OFS;
  float* varp   = out + VAR_OFS;
  float* fwp    = out + FW_OFS;
  float* coords = out + COORD_OFS;
  float* scores = out + SCORE_OFS;

  void *ph0, *pl0, *ph1, *pl1, *pf, *pwh, *pwl, *pcg;
  cudaGetSymbolAddress(&ph0, g_nh0);
  cudaGetSymbolAddress(&pl0, g_nl0);
  cudaGetSymbolAddress(&ph1, g_nh1);
  cudaGetSymbolAddress(&pl1, g_nl1);
  cudaGetSymbolAddress(&pf,  g_f32);
  cudaGetSymbolAddress(&pwh, g_awh);
  cudaGetSymbolAddress(&pwl, g_awl);
  cudaGetSymbolAddress(&pcg, g_cg);
  __nv_bfloat16* Ah = (__nv_bfloat16*)ph0;
  __nv_bfloat16* Al = (__nv_bfloat16*)pl0;
  __nv_bfloat16* Bh = (__nv_bfloat16*)ph1;
  __nv_bfloat16* Bl = (__nv_bfloat16*)pl1;
  float* F32 = (float*)pf;
  __nv_bfloat16* awh = (__nv_bfloat16*)pwh;
  __nv_bfloat16* awl = (__nv_bfloat16*)pwl;
  float* cgp = (float*)pcg;

  cudaFuncSetAttribute(conv3_mma<0>, cudaFuncAttributeMaxDynamicSharedMemorySize, SMEM_CONV);
  cudaFuncSetAttribute(conv3_mma<1>, cudaFuncAttributeMaxDynamicSharedMemorySize, SMEM_CONV);

  transpose_split_kernel<<<dim3(64, 4, NB), 256>>>(x, Ah, Al);
  wtrans_kernel<<<2304, 256>>>(w_s1, g_s1, awh + AW_S1, awl + AW_S1, 589824);
  wtrans_kernel<<<2304, 256>>>(w_s2, g_s2, awh + AW_S2, awl + AW_S2, 589824);
  wtrans_kernel<<<2304, 256>>>(w_h1, g_h1, awh + AW_H1, awl + AW_H1, 589824);
  wtrans_kernel<<<2304, 256>>>(w_o1, g_o1, awh + AW_O1, awl + AW_O1, 589824);
  wtrans_kernel<<<1152, 256>>>(w_v1, g_v1, awh + AW_V1, awl + AW_V1, 294912);

  // stem: x(A) -> s1(B) -> s2(A)
  conv3_mma<0><<<dim3(16, 2, NB), 512, SMEM_CONV>>>(Ah, Al, awh + AW_S1, awl + AW_S1, b_s1, Bh, Bl, nullptr, 256);
  conv3_mma<0><<<dim3(16, 2, NB), 512, SMEM_CONV>>>(Bh, Bl, awh + AW_S2, awl + AW_S2, b_s2, Ah, Al, nullptr, 256);

  // heat branch
  conv3_mma<1><<<dim3(16, 2, NB), 512, SMEM_CONV>>>(Ah, Al, awh + AW_H1, awl + AW_H1, b_h1, nullptr, nullptr, F32, 256);
  conv1x1_kernel<17><<<dim3(16, NB), 256>>>(F32, w_h2, c_h2, heat, 256, 0);
  // offset branch
  conv3_mma<1><<<dim3(16, 2, NB), 512, SMEM_CONV>>>(Ah, Al, awh + AW_O1, awl + AW_O1, b_o1, nullptr, nullptr, F32, 256);
  conv1x1_kernel<34><<<dim3(16, NB), 256>>>(F32, w_o2, c_o2, offp, 256, 0);
  // var branch
  conv3_mma<1><<<dim3(16, 1, NB), 512, SMEM_CONV>>>(Ah, Al, awh + AW_V1, awl + AW_V1, b_v1, nullptr, nullptr, F32, 128);
  conv1x1_kernel<17><<<dim3(16, NB), 256>>>(F32, w_v2, c_v2, varp, 128, 1);

  // epilogue
  softargmax_kernel<<<NB * NK, 256>>>(heat, cgp, scores);
  finalize_kernel<<<3, 256>>>(heat, offp, cgp, alpha, fusion, coords, fwp);

  (void)in_sizes; (void)n_in; (void)out_size;
}